// round 6
// baseline (speedup 1.0000x reference)
#include <cuda_runtime.h>
#include <cuda_fp16.h>
#include <cstdint>
#include <math.h>

// ---------------- problem constants ----------------
#define BB    1024
#define SS    64
#define EE    768
#define HH    12
#define HID   3072
#define MM    (BB*SS)      // 65536 rows
#define N1    (3*EE)       // 2304 fused QKV cols

// ---------------- device scratch (static, no allocations) ----------------
__device__ __half g_hn  [(size_t)MM * EE];    // LN output (reused for LN2)
__device__ __half g_qkv [(size_t)MM * N1];    // fused QKV output
__device__ __half g_h1  [(size_t)MM * HID];   // GELU(MLP1) output
__device__ float  g_x   [(size_t)MM * EE];    // image + attn (residual stream)
__device__ __half g_wqkv[(size_t)N1 * EE];    // [2304][768] K-major
__device__ __half g_w1t [(size_t)HID * EE];   // [3072][768] K-major
__device__ __half g_w2t [(size_t)EE * HID];   // [768][3072] K-major
__device__ float  g_bqkv[N1];

// ---------------- small helpers ----------------
__device__ __forceinline__ uint32_t smem_u32(const void* p) {
    return (uint32_t)__cvta_generic_to_shared(p);
}
__device__ __forceinline__ void cp16(void* s, const void* g) {
    asm volatile("cp.async.cg.shared.global [%0], [%1], 16;\n"
                 :: "r"(smem_u32(s)), "l"(g));
}
__device__ __forceinline__ void ldm4(uint32_t& r0, uint32_t& r1, uint32_t& r2, uint32_t& r3, uint32_t a) {
    asm volatile("ldmatrix.sync.aligned.m8n8.x4.shared.b16 {%0,%1,%2,%3}, [%4];"
                 : "=r"(r0), "=r"(r1), "=r"(r2), "=r"(r3) : "r"(a));
}
__device__ __forceinline__ void mma16816(float* c,
        uint32_t a0, uint32_t a1, uint32_t a2, uint32_t a3,
        uint32_t b0, uint32_t b1) {
    asm volatile(
        "mma.sync.aligned.m16n8k16.row.col.f32.f16.f16.f32 "
        "{%0,%1,%2,%3},{%4,%5,%6,%7},{%8,%9},{%0,%1,%2,%3};"
        : "+f"(c[0]), "+f"(c[1]), "+f"(c[2]), "+f"(c[3])
        : "r"(a0), "r"(a1), "r"(a2), "r"(a3), "r"(b0), "r"(b1));
}
__device__ __forceinline__ float gelu_exact(float v) {
    return 0.5f * v * (1.0f + erff(v * 0.70710678118654752f));
}

// ---------------- weight transpose + fp32->fp16 ----------------
// W is [K][N] fp32 (in,out); Wt is [N][K] fp16 (K-major for MMA B operand)
__global__ void transpose_cvt(const float* __restrict__ W,
                              __half* __restrict__ Wt,
                              int K, int N) {
    __shared__ float t[32][33];
    int n0 = blockIdx.x << 5, k0 = blockIdx.y << 5;
    #pragma unroll
    for (int i = threadIdx.y; i < 32; i += 8)
        t[i][threadIdx.x] = W[(size_t)(k0 + i) * N + n0 + threadIdx.x];
    __syncthreads();
    #pragma unroll
    for (int i = threadIdx.y; i < 32; i += 8)
        Wt[(size_t)(n0 + i) * K + k0 + threadIdx.x] = __float2half_rn(t[threadIdx.x][i]);
}

__global__ void pack_bias(const float* __restrict__ bq,
                          const float* __restrict__ bk,
                          const float* __restrict__ bv) {
    int i = blockIdx.x * 256 + threadIdx.x;
    if (i < N1)
        g_bqkv[i] = (i < EE) ? bq[i] : (i < 2 * EE) ? bk[i - EE] : bv[i - 2 * EE];
}

// ---------------- LayerNorm (row = 768, block = 256 threads) ----------------
__global__ void __launch_bounds__(256) ln_kernel(const float* __restrict__ x,
                                                 const float* __restrict__ g,
                                                 const float* __restrict__ be,
                                                 __half* __restrict__ out) {
    int row = blockIdx.x;
    const float* xr = x + (size_t)row * EE;
    int t = threadIdx.x;
    float v0 = xr[t], v1 = xr[t + 256], v2 = xr[t + 512];
    float s  = v0 + v1 + v2;
    float s2 = v0 * v0 + v1 * v1 + v2 * v2;
    #pragma unroll
    for (int o = 16; o; o >>= 1) {
        s  += __shfl_xor_sync(0xffffffffu, s,  o);
        s2 += __shfl_xor_sync(0xffffffffu, s2, o);
    }
    __shared__ float rs[8], rs2[8];
    int w = t >> 5;
    if ((t & 31) == 0) { rs[w] = s; rs2[w] = s2; }
    __syncthreads();
    float ts = 0.f, ts2 = 0.f;
    #pragma unroll
    for (int i = 0; i < 8; i++) { ts += rs[i]; ts2 += rs2[i]; }
    float mu   = ts * (1.0f / 768.0f);
    float var  = ts2 * (1.0f / 768.0f) - mu * mu;
    float rstd = rsqrtf(var + 1e-6f);
    __half* orow = out + (size_t)row * EE;
    orow[t]       = __float2half_rn((v0 - mu) * rstd * g[t]       + be[t]);
    orow[t + 256] = __float2half_rn((v1 - mu) * rstd * g[t + 256] + be[t + 256]);
    orow[t + 512] = __float2half_rn((v2 - mu) * rstd * g[t + 512] + be[t + 512]);
}

// ---------------- fp16 HMMA GEMM: C[M][N] = A[M][K] * Bt[N][K]^T ----------------
// BM=128 BN=128 BK=32, 256 threads, 8 warps (4m x 2n), warp tile 32x64.
// EPI: 0 = +bias -> fp16 ; 1 = gelu(+bias) -> fp16 ; 2 = +bias +res -> fp32
template<int EPI>
__global__ void __launch_bounds__(256) gemm_fp16(
        const __half* __restrict__ A,
        const __half* __restrict__ Bt,
        const float* __restrict__ bias,
        const float* __restrict__ res,
        void* __restrict__ outp,
        int Kdim, int Ndim) {
    __shared__ __align__(16) __half sA[2][128][40];  // 32 + 8 pad -> 80B rows
    __shared__ __align__(16) __half sB[2][128][40];
    const int m0 = blockIdx.y << 7, n0 = blockIdx.x << 7;
    const int tid = threadIdx.x, lane = tid & 31, warp = tid >> 5;
    const int wm = warp & 3, wn = warp >> 2;

    float acc[2][8][4];
    #pragma unroll
    for (int a = 0; a < 2; a++)
        #pragma unroll
        for (int b = 0; b < 8; b++)
            #pragma unroll
            for (int c = 0; c < 4; c++) acc[a][b][c] = 0.f;

    const int lr = tid >> 2;          // loader row (0..63), +64 for second half
    const int lc = (tid & 3) << 3;    // loader col offset (elems)

    auto load_tile = [&](int st, int kt) {
        int kb = kt << 5;
        #pragma unroll
        for (int i = 0; i < 2; i++) {
            int row = (i << 6) + lr;
            cp16(&sA[st][row][lc], A  + (size_t)(m0 + row) * Kdim + kb + lc);
            cp16(&sB[st][row][lc], Bt + (size_t)(n0 + row) * Kdim + kb + lc);
        }
        asm volatile("cp.async.commit_group;\n" ::);
    };

    const int KT = Kdim >> 5;
    load_tile(0, 0);

    const int la = lane & 15, ka = (lane >> 4) << 3;                 // A frag lanes
    const int nb = (lane & 7) + ((lane >> 4) << 3);                  // B frag lanes
    const int kb2 = ((lane >> 3) & 1) << 3;

    for (int kt = 0; kt < KT; ++kt) {
        int cur = kt & 1;
        if (kt + 1 < KT) {
            load_tile(cur ^ 1, kt + 1);
            asm volatile("cp.async.wait_group 1;\n" ::);
        } else {
            asm volatile("cp.async.wait_group 0;\n" ::);
        }
        __syncthreads();
        #pragma unroll
        for (int kk = 0; kk < 32; kk += 16) {
            uint32_t af[2][4];
            #pragma unroll
            for (int mi = 0; mi < 2; mi++) {
                uint32_t ad = smem_u32(&sA[cur][(wm << 5) + (mi << 4) + la][kk + ka]);
                ldm4(af[mi][0], af[mi][1], af[mi][2], af[mi][3], ad);
            }
            uint32_t bfr[4][4];
            #pragma unroll
            for (int p = 0; p < 4; p++) {
                uint32_t bd = smem_u32(&sB[cur][(wn << 6) + (p << 4) + nb][kk + kb2]);
                ldm4(bfr[p][0], bfr[p][1], bfr[p][2], bfr[p][3], bd);
            }
            #pragma unroll
            for (int mi = 0; mi < 2; mi++)
                #pragma unroll
                for (int nj = 0; nj < 8; nj++) {
                    uint32_t b0 = bfr[nj >> 1][(nj & 1) << 1];
                    uint32_t b1 = bfr[nj >> 1][((nj & 1) << 1) + 1];
                    mma16816(acc[mi][nj], af[mi][0], af[mi][1], af[mi][2], af[mi][3], b0, b1);
                }
        }
        __syncthreads();
    }

    // epilogue
    const int gg = lane >> 2, tc = (lane & 3) << 1;
    #pragma unroll
    for (int mi = 0; mi < 2; mi++) {
        #pragma unroll
        for (int nj = 0; nj < 8; nj++) {
            int row = m0 + (wm << 5) + (mi << 4) + gg;
            int col = n0 + (wn << 6) + (nj << 3) + tc;
            float b0v = bias[col], b1v = bias[col + 1];
            float v00 = acc[mi][nj][0] + b0v, v01 = acc[mi][nj][1] + b1v;
            float v10 = acc[mi][nj][2] + b0v, v11 = acc[mi][nj][3] + b1v;
            if (EPI == 0) {
                __half* o = (__half*)outp;
                *(__half2*)(o + (size_t)row * Ndim + col)       = __floats2half2_rn(v00, v01);
                *(__half2*)(o + (size_t)(row + 8) * Ndim + col) = __floats2half2_rn(v10, v11);
            } else if (EPI == 1) {
                __half* o = (__half*)outp;
                *(__half2*)(o + (size_t)row * Ndim + col) =
                    __floats2half2_rn(gelu_exact(v00), gelu_exact(v01));
                *(__half2*)(o + (size_t)(row + 8) * Ndim + col) =
                    __floats2half2_rn(gelu_exact(v10), gelu_exact(v11));
            } else {
                float* o = (float*)outp;
                size_t i0 = (size_t)row * Ndim + col;
                size_t i1 = (size_t)(row + 8) * Ndim + col;
                o[i0]     = v00 + res[i0];
                o[i0 + 1] = v01 + res[i0 + 1];
                o[i1]     = v10 + res[i1];
                o[i1 + 1] = v11 + res[i1 + 1];
            }
        }
    }
}

// ---------------- attention: one CTA per (b,h) ----------------
// score[s,t] = sum_d q[s,d]k[t,d] / sqrt(768); P = softmax_t(score)
// attn[s,t]  = sum_d v[s,d] P[d,t]
// output flat index within batch is exactly h*4096 + s*64 + t (matches reshape)
__global__ void __launch_bounds__(256) attn_kernel(const __half* __restrict__ qkv,
                                                   const float* __restrict__ image,
                                                   float* __restrict__ x) {
    __shared__ __half sq[64][64], sk[64][64], sv[64][64];
    __shared__ float sp[64][65];
    int bh = blockIdx.x;
    int b = bh / HH, h = bh % HH;
    const __half* base = qkv + (size_t)b * SS * N1 + h * 64;

    // stage q,k,v tiles (16B vectorized)
    for (int i = threadIdx.x; i < 64 * 8; i += 256) {
        int s = i >> 3, c = (i & 7) << 3;
        const __half* rp = base + (size_t)s * N1;
        *(uint4*)&sq[s][c] = *(const uint4*)(rp + c);
        *(uint4*)&sk[s][c] = *(const uint4*)(rp + EE + c);
        *(uint4*)&sv[s][c] = *(const uint4*)(rp + 2 * EE + c);
    }
    __syncthreads();

    int tx = threadIdx.x & 15, ty = threadIdx.x >> 4;
    int r0 = ty << 2, c0 = tx << 2;

    // scores
    float a[4][4];
    #pragma unroll
    for (int i = 0; i < 4; i++)
        #pragma unroll
        for (int j = 0; j < 4; j++) a[i][j] = 0.f;
    for (int d = 0; d < 64; d += 2) {
        float2 qf[4], kf[4];
        #pragma unroll
        for (int i = 0; i < 4; i++) {
            qf[i] = __half22float2(*(const __half2*)&sq[r0 + i][d]);
            kf[i] = __half22float2(*(const __half2*)&sk[c0 + i][d]);
        }
        #pragma unroll
        for (int i = 0; i < 4; i++)
            #pragma unroll
            for (int j = 0; j < 4; j++)
                a[i][j] += qf[i].x * kf[j].x + qf[i].y * kf[j].y;
    }
    const float scale = 0.036084391824351615f;   // 1/sqrt(768)
    #pragma unroll
    for (int i = 0; i < 4; i++)
        #pragma unroll
        for (int j = 0; j < 4; j++)
            sp[r0 + i][c0 + j] = a[i][j] * scale;
    __syncthreads();

    // softmax over rows of sp (8 rows per warp)
    int warp = threadIdx.x >> 5, lane = threadIdx.x & 31;
    for (int rr = 0; rr < 8; rr++) {
        int r = (warp << 3) + rr;
        float v0 = sp[r][lane], v1 = sp[r][lane + 32];
        float m = fmaxf(v0, v1);
        #pragma unroll
        for (int o = 16; o; o >>= 1) m = fmaxf(m, __shfl_xor_sync(0xffffffffu, m, o));
        float e0 = expf(v0 - m), e1 = expf(v1 - m);
        float s = e0 + e1;
        #pragma unroll
        for (int o = 16; o; o >>= 1) s += __shfl_xor_sync(0xffffffffu, s, o);
        float inv = 1.0f / s;
        sp[r][lane] = e0 * inv;
        sp[r][lane + 32] = e1 * inv;
    }
    __syncthreads();

    // attn = V @ P
    float o4[4][4];
    #pragma unroll
    for (int i = 0; i < 4; i++)
        #pragma unroll
        for (int j = 0; j < 4; j++) o4[i][j] = 0.f;
    for (int d = 0; d < 64; d += 2) {
        float2 vf[4];
        float p0[4], p1[4];
        #pragma unroll
        for (int i = 0; i < 4; i++)
            vf[i] = __half22float2(*(const __half2*)&sv[r0 + i][d]);
        #pragma unroll
        for (int j = 0; j < 4; j++) { p0[j] = sp[d][c0 + j]; p1[j] = sp[d + 1][c0 + j]; }
        #pragma unroll
        for (int i = 0; i < 4; i++)
            #pragma unroll
            for (int j = 0; j < 4; j++)
                o4[i][j] += vf[i].x * p0[j] + vf[i].y * p1[j];
    }

    size_t outb = (size_t)b * (SS * EE) + (size_t)h * 4096;
    #pragma unroll
    for (int i = 0; i < 4; i++)
        #pragma unroll
        for (int j = 0; j < 4; j++) {
            int idx = (r0 + i) * 64 + (c0 + j);
            x[outb + idx] = image[outb + idx] + o4[i][j];
        }
}

// ---------------- launch ----------------
extern "C" void kernel_launch(void* const* d_in, const int* in_sizes, int n_in,
                              void* d_out, int out_size) {
    (void)in_sizes; (void)n_in; (void)out_size;
    const float* image = (const float*)d_in[0];
    const float* ln_g  = (const float*)d_in[1];
    const float* ln_b  = (const float*)d_in[2];
    const float* Wq    = (const float*)d_in[3];
    const float* bq    = (const float*)d_in[4];
    const float* Wk    = (const float*)d_in[5];
    const float* bk    = (const float*)d_in[6];
    const float* Wv    = (const float*)d_in[7];
    const float* bv    = (const float*)d_in[8];
    const float* W1    = (const float*)d_in[9];
    const float* b1    = (const float*)d_in[10];
    const float* W2    = (const float*)d_in[11];
    const float* b2    = (const float*)d_in[12];

    __half *hn, *qkv, *h1, *wqkv, *w1t, *w2t;
    float *x, *bqkv;
    cudaGetSymbolAddress((void**)&hn,   g_hn);
    cudaGetSymbolAddress((void**)&qkv,  g_qkv);
    cudaGetSymbolAddress((void**)&h1,   g_h1);
    cudaGetSymbolAddress((void**)&x,    g_x);
    cudaGetSymbolAddress((void**)&wqkv, g_wqkv);
    cudaGetSymbolAddress((void**)&w1t,  g_w1t);
    cudaGetSymbolAddress((void**)&w2t,  g_w2t);
    cudaGetSymbolAddress((void**)&bqkv, g_bqkv);

    dim3 t32(32, 8);
    // weight prep (K-major fp16)
    transpose_cvt<<<dim3(24, 24), t32>>>(Wq, wqkv,                 EE, EE);
    transpose_cvt<<<dim3(24, 24), t32>>>(Wk, wqkv + EE * EE,       EE, EE);
    transpose_cvt<<<dim3(24, 24), t32>>>(Wv, wqkv + 2 * EE * EE,   EE, EE);
    transpose_cvt<<<dim3(96, 24), t32>>>(W1, w1t, EE, HID);
    transpose_cvt<<<dim3(24, 96), t32>>>(W2, w2t, HID, EE);
    pack_bias<<<9, 256>>>(bq, bk, bv);

    // LN1 -> fused QKV GEMM -> attention (+residual) -> LN2 -> MLP
    ln_kernel<<<MM, 256>>>(image, ln_g, ln_b, hn);
    gemm_fp16<0><<<dim3(N1 / 128, MM / 128), 256>>>(hn, wqkv, bqkv, nullptr, qkv, EE, N1);
    attn_kernel<<<BB * HH, 256>>>(qkv, image, x);
    ln_kernel<<<MM, 256>>>(x, ln_g, ln_b, hn);
    gemm_fp16<1><<<dim3(HID / 128, MM / 128), 256>>>(hn, w1t, b1, nullptr, h1, EE, HID);
    gemm_fp16<2><<<dim3(EE / 128, MM / 128), 256>>>(h1, w2t, b2, x, d_out, HID, EE);
}

// round 13
// speedup vs baseline: 1.0341x; 1.0341x over previous
#include <cuda_runtime.h>
#include <cuda_fp16.h>
#include <cstdint>
#include <math.h>

// ---------------- problem constants ----------------
#define BB    1024
#define SS    64
#define EE    768
#define HH    12
#define HID   3072
#define MM    (BB*SS)      // 65536 rows
#define N1    (3*EE)       // 2304 fused QKV cols

// ---------------- GEMM tiling ----------------
#define BM 128
#define BN 256
#define BK 32
#define SA_ST   (128*40)               // halves per stage (A), 8-half pad
#define SB_ST   (256*40)               // halves per stage (B)
#define ST_HALVES (SA_ST + SB_ST)      // 15360 halves = 30720 B
#define GEMM_SMEM (3 * ST_HALVES * 2)  // 92160 B (3 stages)

// ---------------- device scratch (static, no allocations) ----------------
__device__ __half g_hn  [(size_t)MM * EE];    // LN output (reused for LN2)
__device__ __half g_qkv [(size_t)MM * N1];    // fused QKV output
__device__ __half g_h1  [(size_t)MM * HID];   // GELU(MLP1) output
__device__ float  g_x   [(size_t)MM * EE];    // image + attn (residual stream)
__device__ __half g_wqkv[(size_t)N1 * EE];    // [2304][768] K-major
__device__ __half g_w1t [(size_t)HID * EE];   // [3072][768] K-major
__device__ __half g_w2t [(size_t)EE * HID];   // [768][3072] K-major
__device__ float  g_bqkv[N1];

// ---------------- small helpers (sm_80-safe only) ----------------
__device__ __forceinline__ uint32_t smem_u32(const void* p) {
    return (uint32_t)__cvta_generic_to_shared(p);
}
__device__ __forceinline__ void cp16s(uint32_t s, const void* g) {
    asm volatile("cp.async.cg.shared.global [%0], [%1], 16;\n" :: "r"(s), "l"(g));
}
__device__ __forceinline__ void ldm4(uint32_t& r0, uint32_t& r1, uint32_t& r2, uint32_t& r3, uint32_t a) {
    asm volatile("ldmatrix.sync.aligned.m8n8.x4.shared.b16 {%0,%1,%2,%3}, [%4];"
                 : "=r"(r0), "=r"(r1), "=r"(r2), "=r"(r3) : "r"(a));
}
__device__ __forceinline__ void mma16816(float* c,
        uint32_t a0, uint32_t a1, uint32_t a2, uint32_t a3,
        uint32_t b0, uint32_t b1) {
    asm volatile(
        "mma.sync.aligned.m16n8k16.row.col.f32.f16.f16.f32 "
        "{%0,%1,%2,%3},{%4,%5,%6,%7},{%8,%9},{%0,%1,%2,%3};"
        : "+f"(c[0]), "+f"(c[1]), "+f"(c[2]), "+f"(c[3])
        : "r"(a0), "r"(a1), "r"(a2), "r"(a3), "r"(b0), "r"(b1));
}
__device__ __forceinline__ float gelu_exact(float v) {
    return 0.5f * v * (1.0f + erff(v * 0.70710678118654752f));
}

// ---------------- weight transpose + fp32->fp16 ----------------
__global__ void transpose_cvt(const float* __restrict__ W,
                              __half* __restrict__ Wt,
                              int K, int N) {
    __shared__ float t[32][33];
    int n0 = blockIdx.x << 5, k0 = blockIdx.y << 5;
    #pragma unroll
    for (int i = threadIdx.y; i < 32; i += 8)
        t[i][threadIdx.x] = W[(size_t)(k0 + i) * N + n0 + threadIdx.x];
    __syncthreads();
    #pragma unroll
    for (int i = threadIdx.y; i < 32; i += 8)
        Wt[(size_t)(n0 + i) * K + k0 + threadIdx.x] = __float2half_rn(t[threadIdx.x][i]);
}

__global__ void pack_bias(const float* __restrict__ bq,
                          const float* __restrict__ bk,
                          const float* __restrict__ bv) {
    int i = blockIdx.x * 256 + threadIdx.x;
    if (i < N1)
        g_bqkv[i] = (i < EE) ? bq[i] : (i < 2 * EE) ? bk[i - EE] : bv[i - 2 * EE];
}

// ---------------- LayerNorm (row = 768, block = 256 threads) ----------------
__global__ void __launch_bounds__(256) ln_kernel(const float* __restrict__ x,
                                                 const float* __restrict__ g,
                                                 const float* __restrict__ be,
                                                 __half* __restrict__ out) {
    int row = blockIdx.x;
    const float* xr = x + (size_t)row * EE;
    int t = threadIdx.x;
    float v0 = xr[t], v1 = xr[t + 256], v2 = xr[t + 512];
    float s  = v0 + v1 + v2;
    float s2 = v0 * v0 + v1 * v1 + v2 * v2;
    #pragma unroll
    for (int o = 16; o; o >>= 1) {
        s  += __shfl_xor_sync(0xffffffffu, s,  o);
        s2 += __shfl_xor_sync(0xffffffffu, s2, o);
    }
    __shared__ float rs[8], rs2[8];
    int w = t >> 5;
    if ((t & 31) == 0) { rs[w] = s; rs2[w] = s2; }
    __syncthreads();
    float ts = 0.f, ts2 = 0.f;
    #pragma unroll
    for (int i = 0; i < 8; i++) { ts += rs[i]; ts2 += rs2[i]; }
    float mu   = ts * (1.0f / 768.0f);
    float var  = ts2 * (1.0f / 768.0f) - mu * mu;
    float rstd = rsqrtf(var + 1e-6f);
    __half* orow = out + (size_t)row * EE;
    orow[t]       = __float2half_rn((v0 - mu) * rstd * g[t]       + be[t]);
    orow[t + 256] = __float2half_rn((v1 - mu) * rstd * g[t + 256] + be[t + 256]);
    orow[t + 512] = __float2half_rn((v2 - mu) * rstd * g[t + 512] + be[t + 512]);
}

// ---------------- fp16 HMMA GEMM: C[M][N] = A[M][K] * Bt[N][K]^T ----------------
// BM=128 BN=256 BK=32, 3-stage cp.async, 256 threads, 8 warps (2m x 4n),
// warp tile 64x64, one __syncthreads per K-iter.
// EPI: 0 = +bias -> fp16 ; 1 = gelu(+bias) -> fp16 ; 2 = +bias +res -> fp32
template<int EPI>
__global__ void __launch_bounds__(256, 1) gemm_fp16(
        const __half* __restrict__ A,
        const __half* __restrict__ Bt,
        const float* __restrict__ bias,
        const float* __restrict__ res,
        void* __restrict__ outp,
        int Kdim, int Ndim) {
    extern __shared__ __half sm[];
    const int tid = threadIdx.x, lane = tid & 31, warp = tid >> 5;
    const int wm = warp & 1, wn = warp >> 1;          // 2m x 4n warps
    const int m0 = blockIdx.y << 7, n0 = blockIdx.x << 8;

    float acc[4][8][4];
    #pragma unroll
    for (int a = 0; a < 4; a++)
        #pragma unroll
        for (int b = 0; b < 8; b++)
            #pragma unroll
            for (int c = 0; c < 4; c++) acc[a][b][c] = 0.f;

    const int lr = tid >> 2;          // loader row 0..63
    const int lc = (tid & 3) << 3;    // loader col offset (halves)

    auto load_tile = [&](int st, int kt) {
        const int kb = kt << 5;
        __half* sA = sm + st * ST_HALVES;
        __half* sB = sA + SA_ST;
        #pragma unroll
        for (int i = 0; i < 2; i++) {        // A: 128 rows
            int row = (i << 6) + lr;
            cp16s(smem_u32(sA + row * 40 + lc),
                  A + (size_t)(m0 + row) * Kdim + kb + lc);
        }
        #pragma unroll
        for (int i = 0; i < 4; i++) {        // B: 256 rows
            int row = (i << 6) + lr;
            cp16s(smem_u32(sB + row * 40 + lc),
                  Bt + (size_t)(n0 + row) * Kdim + kb + lc);
        }
        asm volatile("cp.async.commit_group;\n" ::);
    };

    const int KT = Kdim >> 5;
    load_tile(0, 0);
    load_tile(1, 1);

    const int la = lane & 15, ka = (lane >> 4) << 3;     // A frag lanes
    const int nb = (lane & 7) + ((lane >> 4) << 3);      // B frag lanes
    const int kb2 = ((lane >> 3) & 1) << 3;

    int st = 0;
    for (int kt = 0; kt < KT; ++kt) {
        if (kt + 1 < KT) asm volatile("cp.async.wait_group 1;\n" ::);
        else             asm volatile("cp.async.wait_group 0;\n" ::);
        __syncthreads();
        __half* sA = sm + st * ST_HALVES;
        __half* sB = sA + SA_ST;
        #pragma unroll
        for (int kk = 0; kk < 32; kk += 16) {
            uint32_t af[4][4];
            #pragma unroll
            for (int mi = 0; mi < 4; mi++) {
                uint32_t ad = smem_u32(sA + ((wm << 6) + (mi << 4) + la) * 40 + kk + ka);
                ldm4(af[mi][0], af[mi][1], af[mi][2], af[mi][3], ad);
            }
            uint32_t bfr[4][4];
            #pragma unroll
            for (int p = 0; p < 4; p++) {
                uint32_t bd = smem_u32(sB + ((wn << 6) + (p << 4) + nb) * 40 + kk + kb2);
                ldm4(bfr[p][0], bfr[p][1], bfr[p][2], bfr[p][3], bd);
            }
            #pragma unroll
            for (int mi = 0; mi < 4; mi++)
                #pragma unroll
                for (int nj = 0; nj < 8; nj++) {
                    uint32_t b0 = bfr[nj >> 1][(nj & 1) << 1];
                    uint32_t b1 = bfr[nj >> 1][((nj & 1) << 1) + 1];
                    mma16816(acc[mi][nj], af[mi][0], af[mi][1], af[mi][2], af[mi][3], b0, b1);
                }
        }
        if (kt + 2 < KT) {
            int wst = st + 2; if (wst >= 3) wst -= 3;
            load_tile(wst, kt + 2);
        }
        if (++st == 3) st = 0;
    }

    // epilogue
    const int gg = lane >> 2, tc = (lane & 3) << 1;
    #pragma unroll
    for (int mi = 0; mi < 4; mi++) {
        #pragma unroll
        for (int nj = 0; nj < 8; nj++) {
            int row = m0 + (wm << 6) + (mi << 4) + gg;
            int col = n0 + (wn << 6) + (nj << 3) + tc;
            float b0v = bias[col], b1v = bias[col + 1];
            float v00 = acc[mi][nj][0] + b0v, v01 = acc[mi][nj][1] + b1v;
            float v10 = acc[mi][nj][2] + b0v, v11 = acc[mi][nj][3] + b1v;
            if (EPI == 0) {
                __half* o = (__half*)outp;
                *(__half2*)(o + (size_t)row * Ndim + col)       = __floats2half2_rn(v00, v01);
                *(__half2*)(o + (size_t)(row + 8) * Ndim + col) = __floats2half2_rn(v10, v11);
            } else if (EPI == 1) {
                __half* o = (__half*)outp;
                *(__half2*)(o + (size_t)row * Ndim + col) =
                    __floats2half2_rn(gelu_exact(v00), gelu_exact(v01));
                *(__half2*)(o + (size_t)(row + 8) * Ndim + col) =
                    __floats2half2_rn(gelu_exact(v10), gelu_exact(v11));
            } else {
                float* o = (float*)outp;
                size_t i0 = (size_t)row * Ndim + col;
                size_t i1 = (size_t)(row + 8) * Ndim + col;
                float2 r0v = *(const float2*)(res + i0);
                float2 r1v = *(const float2*)(res + i1);
                float2 o0; o0.x = v00 + r0v.x; o0.y = v01 + r0v.y;
                float2 o1; o1.x = v10 + r1v.x; o1.y = v11 + r1v.y;
                *(float2*)(o + i0) = o0;
                *(float2*)(o + i1) = o1;
            }
        }
    }
}

// ---------------- attention: one CTA per (b,h) ----------------
// score[s,t] = sum_d q[s,d]k[t,d] / sqrt(768); P = softmax_t(score)
// attn[s,t]  = sum_d v[s,d] P[d,t]
// output flat index within batch is exactly h*4096 + s*64 + t (matches reshape)
__global__ void __launch_bounds__(256) attn_kernel(const __half* __restrict__ qkv,
                                                   const float* __restrict__ image,
                                                   float* __restrict__ x) {
    __shared__ __half sq[64][64], sk[64][64], sv[64][64];
    __shared__ float sp[64][65];
    int bh = blockIdx.x;
    int b = bh / HH, h = bh % HH;
    const __half* base = qkv + (size_t)b * SS * N1 + h * 64;

    for (int i = threadIdx.x; i < 64 * 8; i += 256) {
        int s = i >> 3, c = (i & 7) << 3;
        const __half* rp = base + (size_t)s * N1;
        *(uint4*)&sq[s][c] = *(const uint4*)(rp + c);
        *(uint4*)&sk[s][c] = *(const uint4*)(rp + EE + c);
        *(uint4*)&sv[s][c] = *(const uint4*)(rp + 2 * EE + c);
    }
    __syncthreads();

    int tx = threadIdx.x & 15, ty = threadIdx.x >> 4;
    int r0 = ty << 2, c0 = tx << 2;

    float a[4][4];
    #pragma unroll
    for (int i = 0; i < 4; i++)
        #pragma unroll
        for (int j = 0; j < 4; j++) a[i][j] = 0.f;
    for (int d = 0; d < 64; d += 2) {
        float2 qf[4], kf[4];
        #pragma unroll
        for (int i = 0; i < 4; i++) {
            qf[i] = __half22float2(*(const __half2*)&sq[r0 + i][d]);
            kf[i] = __half22float2(*(const __half2*)&sk[c0 + i][d]);
        }
        #pragma unroll
        for (int i = 0; i < 4; i++)
            #pragma unroll
            for (int j = 0; j < 4; j++)
                a[i][j] += qf[i].x * kf[j].x + qf[i].y * kf[j].y;
    }
    const float scale = 0.036084391824351615f;   // 1/sqrt(768)
    #pragma unroll
    for (int i = 0; i < 4; i++)
        #pragma unroll
        for (int j = 0; j < 4; j++)
            sp[r0 + i][c0 + j] = a[i][j] * scale;
    __syncthreads();

    int warp = threadIdx.x >> 5, lane = threadIdx.x & 31;
    for (int rr = 0; rr < 8; rr++) {
        int r = (warp << 3) + rr;
        float v0 = sp[r][lane], v1 = sp[r][lane + 32];
        float m = fmaxf(v0, v1);
        #pragma unroll
        for (int o = 16; o; o >>= 1) m = fmaxf(m, __shfl_xor_sync(0xffffffffu, m, o));
        float e0 = expf(v0 - m), e1 = expf(v1 - m);
        float s = e0 + e1;
        #pragma unroll
        for (int o = 16; o; o >>= 1) s += __shfl_xor_sync(0xffffffffu, s, o);
        float inv = 1.0f / s;
        sp[r][lane] = e0 * inv;
        sp[r][lane + 32] = e1 * inv;
    }
    __syncthreads();

    float o4[4][4];
    #pragma unroll
    for (int i = 0; i < 4; i++)
        #pragma unroll
        for (int j = 0; j < 4; j++) o4[i][j] = 0.f;
    for (int d = 0; d < 64; d += 2) {
        float2 vf[4];
        float p0[4], p1[4];
        #pragma unroll
        for (int i = 0; i < 4; i++)
            vf[i] = __half22float2(*(const __half2*)&sv[r0 + i][d]);
        #pragma unroll
        for (int j = 0; j < 4; j++) { p0[j] = sp[d][c0 + j]; p1[j] = sp[d + 1][c0 + j]; }
        #pragma unroll
        for (int i = 0; i < 4; i++)
            #pragma unroll
            for (int j = 0; j < 4; j++)
                o4[i][j] += vf[i].x * p0[j] + vf[i].y * p1[j];
    }

    size_t outb = (size_t)b * (SS * EE) + (size_t)h * 4096;
    #pragma unroll
    for (int i = 0; i < 4; i++)
        #pragma unroll
        for (int j = 0; j < 4; j++) {
            int idx = (r0 + i) * 64 + (c0 + j);
            x[outb + idx] = image[outb + idx] + o4[i][j];
        }
}

// ---------------- launch ----------------
extern "C" void kernel_launch(void* const* d_in, const int* in_sizes, int n_in,
                              void* d_out, int out_size) {
    (void)in_sizes; (void)n_in; (void)out_size;
    const float* image = (const float*)d_in[0];
    const float* ln_g  = (const float*)d_in[1];
    const float* ln_b  = (const float*)d_in[2];
    const float* Wq    = (const float*)d_in[3];
    const float* bq    = (const float*)d_in[4];
    const float* Wk    = (const float*)d_in[5];
    const float* bk    = (const float*)d_in[6];
    const float* Wv    = (const float*)d_in[7];
    const float* bv    = (const float*)d_in[8];
    const float* W1    = (const float*)d_in[9];
    const float* b1    = (const float*)d_in[10];
    const float* W2    = (const float*)d_in[11];
    const float* b2    = (const float*)d_in[12];

    __half *hn, *qkv, *h1, *wqkv, *w1t, *w2t;
    float *x, *bqkv;
    cudaGetSymbolAddress((void**)&hn,   g_hn);
    cudaGetSymbolAddress((void**)&qkv,  g_qkv);
    cudaGetSymbolAddress((void**)&h1,   g_h1);
    cudaGetSymbolAddress((void**)&x,    g_x);
    cudaGetSymbolAddress((void**)&wqkv, g_wqkv);
    cudaGetSymbolAddress((void**)&w1t,  g_w1t);
    cudaGetSymbolAddress((void**)&w2t,  g_w2t);
    cudaGetSymbolAddress((void**)&bqkv, g_bqkv);

    cudaFuncSetAttribute(gemm_fp16<0>, cudaFuncAttributeMaxDynamicSharedMemorySize, GEMM_SMEM);
    cudaFuncSetAttribute(gemm_fp16<1>, cudaFuncAttributeMaxDynamicSharedMemorySize, GEMM_SMEM);
    cudaFuncSetAttribute(gemm_fp16<2>, cudaFuncAttributeMaxDynamicSharedMemorySize, GEMM_SMEM);

    dim3 t32(32, 8);
    transpose_cvt<<<dim3(24, 24), t32>>>(Wq, wqkv,               EE, EE);
    transpose_cvt<<<dim3(24, 24), t32>>>(Wk, wqkv + EE * EE,     EE, EE);
    transpose_cvt<<<dim3(24, 24), t32>>>(Wv, wqkv + 2 * EE * EE, EE, EE);
    transpose_cvt<<<dim3(96, 24), t32>>>(W1, w1t, EE, HID);
    transpose_cvt<<<dim3(24, 96), t32>>>(W2, w2t, HID, EE);
    pack_bias<<<9, 256>>>(bq, bk, bv);

    // LN1 -> fused QKV GEMM -> attention (+residual) -> LN2 -> MLP
    ln_kernel<<<MM, 256>>>(image, ln_g, ln_b, hn);
    gemm_fp16<0><<<dim3(N1 / BN, MM / BM), 256, GEMM_SMEM>>>(hn, wqkv, bqkv, nullptr, qkv, EE, N1);
    attn_kernel<<<BB * HH, 256>>>(qkv, image, x);
    ln_kernel<<<MM, 256>>>(x, ln_g, ln_b, hn);
    gemm_fp16<1><<<dim3(HID / BN, MM / BM), 256, GEMM_SMEM>>>(hn, w1t, b1, nullptr, h1, EE, HID);
    gemm_fp16<2><<<dim3(EE / BN, MM / BM), 256, GEMM_SMEM>>>(h1, w2t, b2, x, d_out, HID, EE);
}